// round 17
// baseline (speedup 1.0000x reference)
#include <cuda_runtime.h>
#include <cuda_bf16.h>
#include <cuda_fp16.h>
#include <cstdint>

#define N_NODES 10000
#define E_EDGES 160000
#define IN_CH   14
#define HID     128
#define HEADS   8
#define OUT_CH  4
#define FEAT    (HEADS*HID)   // 1024

// ---------------- scratch (static device memory; no allocations) ----------------
__device__ __half g_h16[(size_t)N_NODES * FEAT];    // fp16 h (layer1, then layer2)
__device__ __half g_hB16[(size_t)N_NODES * FEAT];   // fp16 agg1 output (GEMM A input)
__device__ __half g_W2T16[(size_t)FEAT * FEAT];     // fp16 W2 transposed (GEMM B input)
__device__ float  g_wt[IN_CH * 16];                 // W1 folded with a_src1/a_dst1
__device__ float  g_M2[(size_t)FEAT * 16];          // W2 folded with a_src2/a_dst2
__device__ float  g_als[N_NODES * HEADS];
__device__ float  g_ald[N_NODES * HEADS];
__device__ float  g_als2[N_NODES * HEADS];
__device__ float  g_ald2[N_NODES * HEADS];
__device__ float  g_h3[N_NODES * OUT_CH];
__device__ float  g_als3[N_NODES];
__device__ float  g_ald3[N_NODES];
__device__ int    g_deg[N_NODES];       // zero-init; re-zeroed by agg3 tail
__device__ int    g_cursor[N_NODES];    // ditto
__device__ int    g_rowptr[N_NODES + 1];
__device__ int    g_srcs[E_EDGES];
__device__ int    g_is64;

// ---------------- small PTX helpers ----------------
__device__ __forceinline__ uint32_t smem_u32(const void* p) {
    uint32_t a;
    asm("{ .reg .u64 t; cvta.to.shared.u64 t, %1; cvt.u32.u64 %0, t; }" : "=r"(a) : "l"(p));
    return a;
}

__device__ __forceinline__ void cp_async16(uint32_t s, const void* g, bool pred) {
    int sz = pred ? 16 : 0;
    asm volatile("cp.async.cg.shared.global [%0], [%1], 16, %2;\n"
                 :: "r"(s), "l"(g), "r"(sz) : "memory");
}
#define CP_COMMIT()  asm volatile("cp.async.commit_group;" ::: "memory")
#define CP_WAIT0()   asm volatile("cp.async.wait_group 0;" ::: "memory")

__device__ __forceinline__ void mma_f16(float* c, const uint32_t* a, uint32_t b0, uint32_t b1) {
    asm volatile(
        "mma.sync.aligned.m16n8k16.row.col.f32.f16.f16.f32 "
        "{%0,%1,%2,%3}, {%4,%5,%6,%7}, {%8,%9}, {%0,%1,%2,%3};"
        : "+f"(c[0]), "+f"(c[1]), "+f"(c[2]), "+f"(c[3])
        : "r"(a[0]), "r"(a[1]), "r"(a[2]), "r"(a[3]), "r"(b0), "r"(b1));
}

__device__ __forceinline__ float leaky(float e) {
    return e > 0.f ? e : 0.2f * e;
}

// ---------------- edge index access (int32 vs int64 detected at runtime) --------
__device__ __forceinline__ int edge_val(const void* idx, int is64, long i) {
    if (is64) return (int)((const long long*)idx)[i];
    return ((const int*)idx)[i];
}

__device__ __forceinline__ int detect_is64(const int* p) {
    int is64 = 1;
    for (int k = 0; k < 64; k++) {
        if (p[2*k + 1] != 0) { is64 = 0; break; }
    }
    return is64;
}

// ---------------- wtilde: fold a_src1/a_dst1 into W1 -> g_wt[14][16] ------------
__global__ void wtilde_kernel(const float* __restrict__ W1,
                              const float* __restrict__ as1,
                              const float* __restrict__ ad1) {
    int t = threadIdx.x;
    if (t < IN_CH * 16) {
        int k = t >> 4, o = t & 15;
        const float* a = (o < 8) ? as1 : ad1;
        int hh = o & 7;
        float s = 0.f;
        for (int c = 0; c < HID; c++)
            s += W1[k * FEAT + hh * HID + c] * a[hh * HID + c];
        g_wt[k * 16 + o] = s;
    }
}

// ---------------- prep kernel: 4 segments ----------------
// A [0,625):        gemm1 -> g_h16 + layer-1 logits from x @ g_wt
// B [625,1649):     W2 transpose -> fp16 g_W2T16
// C [1649,1777):    M2 = W2 folded with a_src2/a_dst2 (warp per W2 row)
// D [1777,2402):    edge histogram (count), local is64 detection
#define G1N 16
#define SEG_A (N_NODES / G1N)                 // 625
#define SEG_B (32 * 32)                       // 1024
#define SEG_C (FEAT / 8)                      // 128
#define SEG_D ((E_EDGES + 255) / 256)         // 625
__global__ __launch_bounds__(256) void prep_kernel(const float* __restrict__ x,
                                                   const float* __restrict__ W1,
                                                   const float* __restrict__ W2,
                                                   const float* __restrict__ a_src2,
                                                   const float* __restrict__ a_dst2,
                                                   const void* __restrict__ eidx) {
    int t = threadIdx.x;
    int b = blockIdx.x;
    if (b == 0 && t == 0) g_is64 = detect_is64((const int*)eidx);

    if (b < SEG_A) {
        // ---- layer-1 GEMM [16,14]@[14,1024] -> fp16, plus logits ----
        __shared__ float xs[G1N * IN_CH];
        int nb = b * G1N;
        if (t < G1N * IN_CH) xs[t] = x[nb * IN_CH + t];
        __syncthreads();
#pragma unroll
        for (int j = 0; j < 4; j++) {
            int c = t + j * 256;
            float w[IN_CH];
#pragma unroll
            for (int k = 0; k < IN_CH; k++) w[k] = W1[k * FEAT + c];
            for (int n = 0; n < G1N; n++) {
                float acc = 0.f;
#pragma unroll
                for (int k = 0; k < IN_CH; k++) acc += xs[n * IN_CH + k] * w[k];
                g_h16[(size_t)(nb + n) * FEAT + c] = __float2half_rn(acc);
            }
        }
        // logits: thread = (node, output)
        {
            int node = t >> 4, o = t & 15;
            float s = 0.f;
#pragma unroll
            for (int k = 0; k < IN_CH; k++) s += xs[node * IN_CH + k] * g_wt[k * 16 + o];
            if (o < 8) g_als[(nb + node) * HEADS + o] = s;
            else       g_ald[(nb + node) * HEADS + (o - 8)] = s;
        }
    } else if (b < SEG_A + SEG_B) {
        // ---- W2 transpose to fp16 ----
        __shared__ float tt[32][33];
        int tb = b - SEG_A;
        int bx = (tb & 31) * 32, by = (tb >> 5) * 32;
        int tx = t & 31, ty = t >> 5;   // 32 x 8
        int xg = bx + tx;
#pragma unroll
        for (int j = 0; j < 32; j += 8) tt[ty + j][tx] = W2[(size_t)(by + ty + j) * FEAT + xg];
        __syncthreads();
        int x2 = by + tx;
        int y2 = bx + ty;
#pragma unroll
        for (int j = 0; j < 32; j += 8)
            g_W2T16[(size_t)(y2 + j) * FEAT + x2] = __float2half_rn(tt[tx][ty + j]);
    } else if (b < SEG_A + SEG_B + SEG_C) {
        // ---- M2[k][o]: warp per W2 row k; lane covers 32 cols (single head) ----
        int k = (b - (SEG_A + SEG_B)) * 8 + (t >> 5);
        int lane = t & 31;
        int hh = lane >> 2;
        const float* wrow = W2 + (size_t)k * FEAT;
        float ps = 0.f, pd = 0.f;
#pragma unroll
        for (int q = 0; q < 8; q++) {
            int c = lane * 32 + q * 4;
            float4 v = *(const float4*)&wrow[c];
            float4 a = *(const float4*)&a_src2[c];
            float4 d = *(const float4*)&a_dst2[c];
            ps += v.x * a.x + v.y * a.y + v.z * a.z + v.w * a.w;
            pd += v.x * d.x + v.y * d.y + v.z * d.z + v.w * d.w;
        }
        ps += __shfl_xor_sync(~0u, ps, 1); ps += __shfl_xor_sync(~0u, ps, 2);
        pd += __shfl_xor_sync(~0u, pd, 1); pd += __shfl_xor_sync(~0u, pd, 2);
        if ((lane & 3) == 0) {
            g_M2[k * 16 + hh]     = ps;
            g_M2[k * 16 + 8 + hh] = pd;
        }
    } else {
        // ---- edge histogram (count) with local is64 detection ----
        __shared__ int sis64;
        if (t == 0) sis64 = detect_is64((const int*)eidx);
        __syncthreads();
        int e = (b - (SEG_A + SEG_B + SEG_C)) * 256 + t;
        if (e < E_EDGES) {
            int d = edge_val(eidx, sis64, (long)E_EDGES + e);
            atomicAdd(&g_deg[d], 1);
        }
    }
}

// ---------------- CSR scan + scatter ----------------
__global__ void scan_kernel() {
    __shared__ int wsum[32];
    int t = threadIdx.x, lane = t & 31, w = t >> 5;
    const int CH = (N_NODES + 1023) / 1024;  // 10
    int base = t * CH;
    int s = 0;
#pragma unroll
    for (int i = 0; i < CH; i++) {
        int idx = base + i;
        if (idx < N_NODES) s += g_deg[idx];
    }
    int v = s;
#pragma unroll
    for (int off = 1; off < 32; off <<= 1) {
        int u = __shfl_up_sync(~0u, v, off);
        if (lane >= off) v += u;
    }
    if (lane == 31) wsum[w] = v;
    __syncthreads();
    if (w == 0) {
        int xv = wsum[lane];
#pragma unroll
        for (int off = 1; off < 32; off <<= 1) {
            int u = __shfl_up_sync(~0u, xv, off);
            if (lane >= off) xv += u;
        }
        wsum[lane] = xv;
    }
    __syncthreads();
    int excl = v - s + (w > 0 ? wsum[w - 1] : 0);
    int run = excl;
#pragma unroll
    for (int i = 0; i < CH; i++) {
        int idx = base + i;
        if (idx < N_NODES) { g_rowptr[idx] = run; run += g_deg[idx]; }
    }
    if (t == 1023) g_rowptr[N_NODES] = run;
}

__global__ void scatter_kernel(const void* idx) {
    int e = blockIdx.x * blockDim.x + threadIdx.x;
    if (e < E_EDGES) {
        int f = g_is64;
        int s = edge_val(idx, f, e);
        int d = edge_val(idx, f, (long)E_EDGES + e);
        int pos = g_rowptr[d] + atomicAdd(&g_cursor[d], 1);
        g_srcs[pos] = s;
    }
}

// ---------------- fused per-node softmax + aggregate (heads=8, C=128) -----------
// Gathers fp16 g_h16, accumulates fp32. j-loop unrolled x4 (s_alpha zero-padded).
// MODE 0: write fp16 to g_hB16 + compute layer-2 logits via g_M2 -> g_als2/g_ald2
// MODE 1: fuse layer-3 projection, emit h3/als3/ald3
template <int MODE>
__global__ __launch_bounds__(256) void agg_kernel(const float* __restrict__ als,
                                                  const float* __restrict__ ald,
                                                  const float* __restrict__ bias,
                                                  const float* __restrict__ W3,
                                                  const float* __restrict__ as3,
                                                  const float* __restrict__ ad3) {
    int n = blockIdx.x;
    int t = threadIdx.x, w = t >> 5, lane = t & 31;
    __shared__ float s_alpha[HEADS][32];
    __shared__ int   s_src[32];
    __shared__ float s_p[HEADS][16];
    __shared__ float s_h3[4];

    int start = g_rowptr[n];
    int cnt   = g_rowptr[n + 1] - start;   // self-loop added implicitly at i==cnt

    float aldn = ald[n * HEADS + w];

    // single-pass online softmax stats
    float m = -1e30f, z = 0.f;
    for (int i = lane; i <= cnt; i += 32) {
        int s = (i < cnt) ? g_srcs[start + i] : n;
        float e = leaky(als[s * HEADS + w] + aldn);
        float mn = fmaxf(m, e);
        z = z * expf(m - mn) + expf(e - mn);
        m = mn;
    }
#pragma unroll
    for (int off = 16; off; off >>= 1) {
        float mo = __shfl_xor_sync(~0u, m, off);
        float zo = __shfl_xor_sync(~0u, z, off);
        float mn = fmaxf(m, mo);
        z = z * expf(m - mn) + zo * expf(mo - mn);
        m = mn;
    }
    float iz = 1.f / (z + 1e-16f);

    // chunked aggregate with x4-unrolled consume (alpha zero-padded, src clamped)
    float4 acc = make_float4(0.f, 0.f, 0.f, 0.f);
    const int cbase = w * HID + lane * 4;
    for (int base = 0; base <= cnt; base += 32) {
        int i = base + lane;
        int s = n;
        float a = 0.f;
        if (i <= cnt) {
            if (i < cnt) s = g_srcs[start + i];
            float e = leaky(als[s * HEADS + w] + aldn);
            a = expf(e - m) * iz;
        }
        s_alpha[w][lane] = a;
        if (w == 0) s_src[lane] = s;
        __syncthreads();
        int lim4 = (min(32, cnt + 1 - base) + 3) & ~3;
        for (int j = 0; j < lim4; j += 4) {
            float a0 = s_alpha[w][j + 0], a1 = s_alpha[w][j + 1];
            float a2 = s_alpha[w][j + 2], a3 = s_alpha[w][j + 3];
            uint2 v0 = *(const uint2*)&g_h16[(size_t)s_src[j + 0] * FEAT + cbase];
            uint2 v1 = *(const uint2*)&g_h16[(size_t)s_src[j + 1] * FEAT + cbase];
            uint2 v2 = *(const uint2*)&g_h16[(size_t)s_src[j + 2] * FEAT + cbase];
            uint2 v3 = *(const uint2*)&g_h16[(size_t)s_src[j + 3] * FEAT + cbase];
            float2 f;
            f = __half22float2(*reinterpret_cast<const __half2*>(&v0.x));
            acc.x += a0 * f.x; acc.y += a0 * f.y;
            f = __half22float2(*reinterpret_cast<const __half2*>(&v0.y));
            acc.z += a0 * f.x; acc.w += a0 * f.y;
            f = __half22float2(*reinterpret_cast<const __half2*>(&v1.x));
            acc.x += a1 * f.x; acc.y += a1 * f.y;
            f = __half22float2(*reinterpret_cast<const __half2*>(&v1.y));
            acc.z += a1 * f.x; acc.w += a1 * f.y;
            f = __half22float2(*reinterpret_cast<const __half2*>(&v2.x));
            acc.x += a2 * f.x; acc.y += a2 * f.y;
            f = __half22float2(*reinterpret_cast<const __half2*>(&v2.y));
            acc.z += a2 * f.x; acc.w += a2 * f.y;
            f = __half22float2(*reinterpret_cast<const __half2*>(&v3.x));
            acc.x += a3 * f.x; acc.y += a3 * f.y;
            f = __half22float2(*reinterpret_cast<const __half2*>(&v3.y));
            acc.z += a3 * f.x; acc.w += a3 * f.y;
        }
        __syncthreads();
    }
    float4 b4 = *(const float4*)&bias[cbase];
    acc.x = fmaxf(acc.x + b4.x, 0.f);
    acc.y = fmaxf(acc.y + b4.y, 0.f);
    acc.z = fmaxf(acc.z + b4.z, 0.f);
    acc.w = fmaxf(acc.w + b4.w, 0.f);

    if (MODE == 1) {
        // project through W3 [1024,4]; block-reduce; emit h3/als3/ald3
        float p0, p1, p2, p3;
        {
            float4 w0 = *(const float4*)&W3[(cbase + 0) * 4];
            float4 w1 = *(const float4*)&W3[(cbase + 1) * 4];
            float4 w2 = *(const float4*)&W3[(cbase + 2) * 4];
            float4 w3v = *(const float4*)&W3[(cbase + 3) * 4];
            p0 = acc.x * w0.x + acc.y * w1.x + acc.z * w2.x + acc.w * w3v.x;
            p1 = acc.x * w0.y + acc.y * w1.y + acc.z * w2.y + acc.w * w3v.y;
            p2 = acc.x * w0.z + acc.y * w1.z + acc.z * w2.z + acc.w * w3v.z;
            p3 = acc.x * w0.w + acc.y * w1.w + acc.z * w2.w + acc.w * w3v.w;
        }
#pragma unroll
        for (int off = 16; off; off >>= 1) {
            p0 += __shfl_xor_sync(~0u, p0, off);
            p1 += __shfl_xor_sync(~0u, p1, off);
            p2 += __shfl_xor_sync(~0u, p2, off);
            p3 += __shfl_xor_sync(~0u, p3, off);
        }
        if (lane == 0) {
            s_p[w][0] = p0; s_p[w][1] = p1; s_p[w][2] = p2; s_p[w][3] = p3;
        }
        __syncthreads();
        if (t < 4) {
            float v = 0.f;
#pragma unroll
            for (int ww = 0; ww < HEADS; ww++) v += s_p[ww][t];
            g_h3[n * 4 + t] = v;
            s_h3[t] = v;
        }
        __syncthreads();
        if (t == 0) {
            float ss = 0.f, sd = 0.f;
#pragma unroll
            for (int o = 0; o < 4; o++) {
                ss += s_h3[o] * as3[o];
                sd += s_h3[o] * ad3[o];
            }
            g_als3[n] = ss;
            g_ald3[n] = sd;
        }
    } else {
        // fp16 output (GEMM A input)
        __half2 o0 = __floats2half2_rn(acc.x, acc.y);
        __half2 o1 = __floats2half2_rn(acc.z, acc.w);
        uint2 pk;
        pk.x = *reinterpret_cast<uint32_t*>(&o0);
        pk.y = *reinterpret_cast<uint32_t*>(&o1);
        *(uint2*)&g_hB16[(size_t)n * FEAT + cbase] = pk;
        // layer-2 logits: als2/ald2 = A16 @ M2 (from the rounded values)
        float2 r0 = __half22float2(o0), r1 = __half22float2(o1);
        const float4* m0 = (const float4*)&g_M2[(size_t)(cbase + 0) * 16];
        const float4* m1 = (const float4*)&g_M2[(size_t)(cbase + 1) * 16];
        const float4* m2 = (const float4*)&g_M2[(size_t)(cbase + 2) * 16];
        const float4* m3 = (const float4*)&g_M2[(size_t)(cbase + 3) * 16];
#pragma unroll
        for (int hf = 0; hf < 2; hf++) {
            float p[8];
#pragma unroll
            for (int q = 0; q < 2; q++) {
                float4 a0 = m0[hf * 2 + q], a1 = m1[hf * 2 + q];
                float4 a2 = m2[hf * 2 + q], a3 = m3[hf * 2 + q];
                p[q*4+0] = r0.x*a0.x + r0.y*a1.x + r1.x*a2.x + r1.y*a3.x;
                p[q*4+1] = r0.x*a0.y + r0.y*a1.y + r1.x*a2.y + r1.y*a3.y;
                p[q*4+2] = r0.x*a0.z + r0.y*a1.z + r1.x*a2.z + r1.y*a3.z;
                p[q*4+3] = r0.x*a0.w + r0.y*a1.w + r1.x*a2.w + r1.y*a3.w;
            }
#pragma unroll
            for (int off = 16; off; off >>= 1) {
#pragma unroll
                for (int q = 0; q < 8; q++) p[q] += __shfl_xor_sync(~0u, p[q], off);
            }
            if (lane == 0) {
#pragma unroll
                for (int q = 0; q < 8; q++) s_p[w][hf * 8 + q] = p[q];
            }
        }
        __syncthreads();
        if (t < 16) {
            float v = 0.f;
#pragma unroll
            for (int ww = 0; ww < HEADS; ww++) v += s_p[ww][t];
            if (t < 8) g_als2[n * HEADS + t] = v;
            else       g_ald2[n * HEADS + (t - 8)] = v;
        }
    }
}

// ---------------- fp16 mma.sync GEMM: h2 = A16[M,1024] @ W2 (BT16), fp16 out ----
#define LDH   40                      // halves per smem row (32 + 8 pad)
#define TBUF16 (128 * LDH * 2)        // bytes per tile (10240)
#define STG16  (2 * TBUF16)           // A+B per stage (20480)
#define NIT   32                      // 1024 / 32

__device__ __forceinline__ void load_tiles16(
    const __half* __restrict__ A, const __half* __restrict__ BT,
    uint32_t sA, uint32_t sB, int row0, int n0, int k0, int M, int tid)
{
#pragma unroll
    for (int j = 0; j < 2; j++) {
        int f = tid + j * 256;            // 0..511
        int r = f >> 2;                   // 0..127
        int c = f & 3;                    // 16B chunk (8 halves)
        uint32_t so = (uint32_t)(r * LDH + c * 8) * 2;
        bool ok = (row0 + r) < M;
        int ar = ok ? (row0 + r) : 0;
        cp_async16(sA + so, A  + (size_t)ar * FEAT + k0 + c * 8, ok);
        cp_async16(sB + so, BT + (size_t)(n0 + r) * FEAT + k0 + c * 8, true);
    }
}

__global__ __launch_bounds__(256) void f16_gemm_kernel(
    const __half* __restrict__ A, const __half* __restrict__ BT, int M)
{
    extern __shared__ char dsm[];
    const uint32_t sbase = smem_u32(dsm);
    int tid = threadIdx.x;
    int wid = tid >> 5, lane = tid & 31;
    int grp = lane >> 2, tig = lane & 3;
    int wm = (wid & 1) * 64;
    int wn = (wid >> 1) * 32;
    int row0 = blockIdx.y * 128, n0 = blockIdx.x * 128;

    float acc[4][4][4];
#pragma unroll
    for (int i = 0; i < 4; i++)
#pragma unroll
        for (int j = 0; j < 4; j++)
#pragma unroll
            for (int k = 0; k < 4; k++) acc[i][j][k] = 0.f;

    load_tiles16(A, BT, sbase, sbase + TBUF16, row0, n0, 0, M, tid);
    CP_COMMIT();

    for (int it = 0; it < NIT; it++) {
        CP_WAIT0();
        __syncthreads();
        int cb = it & 1;
        if (it + 1 < NIT) {
            uint32_t nb = sbase + (cb ^ 1) * STG16;
            load_tiles16(A, BT, nb, nb + TBUF16, row0, n0, (it + 1) * 32, M, tid);
            CP_COMMIT();
        }
        const uint32_t* As2 = (const uint32_t*)(dsm + cb * STG16);
        const uint32_t* Bs2 = (const uint32_t*)(dsm + cb * STG16 + TBUF16);
#pragma unroll
        for (int ks = 0; ks < 2; ks++) {
            int kb = ks * 8 + tig;
            uint32_t a[4][4];
#pragma unroll
            for (int mt = 0; mt < 4; mt++) {
                int r0 = wm + mt * 16 + grp;
                a[mt][0] = As2[r0 * (LDH/2) + kb];
                a[mt][1] = As2[(r0 + 8) * (LDH/2) + kb];
                a[mt][2] = As2[r0 * (LDH/2) + kb + 4];
                a[mt][3] = As2[(r0 + 8) * (LDH/2) + kb + 4];
            }
#pragma unroll
            for (int nt = 0; nt < 4; nt++) {
                int rn = wn + nt * 8 + grp;
                uint32_t b0 = Bs2[rn * (LDH/2) + kb];
                uint32_t b1 = Bs2[rn * (LDH/2) + kb + 4];
#pragma unroll
                for (int mt = 0; mt < 4; mt++) mma_f16(acc[mt][nt], a[mt], b0, b1);
            }
        }
        __syncthreads();
    }

    // epilogue: fp16 h2 only (logits come from A @ M2, computed in agg1)
#pragma unroll
    for (int mt = 0; mt < 4; mt++) {
        int gr = row0 + wm + mt * 16 + grp;
#pragma unroll
        for (int nt = 0; nt < 4; nt++) {
            int gc = n0 + wn + nt * 8 + 2 * tig;
            if (gr < M)
                *(__half2*)&g_h16[(size_t)gr * FEAT + gc] =
                    __floats2half2_rn(acc[mt][nt][0], acc[mt][nt][1]);
            if (gr + 8 < M)
                *(__half2*)&g_h16[(size_t)(gr + 8) * FEAT + gc] =
                    __floats2half2_rn(acc[mt][nt][2], acc[mt][nt][3]);
        }
    }
}

// ---------------- layer-3 aggregation + deg/cursor re-zero for next replay ------
__global__ __launch_bounds__(256) void agg3_kernel(const float* __restrict__ b3,
                                                   float* __restrict__ out) {
    {
        int gid = blockIdx.x * blockDim.x + threadIdx.x;
        if (gid < N_NODES) { g_deg[gid] = 0; g_cursor[gid] = 0; }
    }
    int n = (blockIdx.x * blockDim.x + threadIdx.x) >> 5;
    int lane = threadIdx.x & 31;
    if (n >= N_NODES) return;
    int start = g_rowptr[n];
    int cnt   = g_rowptr[n + 1] - start;
    float aldn = g_ald3[n];
    float mx = -1e30f;
    for (int i = lane; i <= cnt; i += 32) {
        int s = (i < cnt) ? g_srcs[start + i] : n;
        mx = fmaxf(mx, leaky(g_als3[s] + aldn));
    }
#pragma unroll
    for (int off = 16; off; off >>= 1) mx = fmaxf(mx, __shfl_xor_sync(~0u, mx, off));
    float z = 0.f;
    float c0 = 0.f, c1 = 0.f, c2 = 0.f, c3 = 0.f;
    for (int i = lane; i <= cnt; i += 32) {
        int s = (i < cnt) ? g_srcs[start + i] : n;
        float e = leaky(g_als3[s] + aldn);
        float ex = expf(e - mx);
        z += ex;
        c0 += ex * g_h3[s * 4 + 0];
        c1 += ex * g_h3[s * 4 + 1];
        c2 += ex * g_h3[s * 4 + 2];
        c3 += ex * g_h3[s * 4 + 3];
    }
#pragma unroll
    for (int off = 16; off; off >>= 1) {
        z  += __shfl_xor_sync(~0u, z, off);
        c0 += __shfl_xor_sync(~0u, c0, off);
        c1 += __shfl_xor_sync(~0u, c1, off);
        c2 += __shfl_xor_sync(~0u, c2, off);
        c3 += __shfl_xor_sync(~0u, c3, off);
    }
    float iz = 1.f / (z + 1e-16f);
    if (lane == 0) {
        out[n * 4 + 0] = fmaxf(c0 * iz + b3[0], 0.f);
        out[n * 4 + 1] = fmaxf(c1 * iz + b3[1], 0.f);
        out[n * 4 + 2] = fmaxf(c2 * iz + b3[2], 0.f);
        out[n * 4 + 3] = fmaxf(c3 * iz + b3[3], 0.f);
    }
}

// ---------------- launch ----------------
extern "C" void kernel_launch(void* const* d_in, const int* in_sizes, int n_in,
                              void* d_out, int out_size) {
    const float* x      = (const float*)d_in[0];
    const void*  eidx   = d_in[1];
    const float* W1     = (const float*)d_in[2];
    const float* a_src1 = (const float*)d_in[3];
    const float* a_dst1 = (const float*)d_in[4];
    const float* b1     = (const float*)d_in[5];
    const float* W2     = (const float*)d_in[6];
    const float* a_src2 = (const float*)d_in[7];
    const float* a_dst2 = (const float*)d_in[8];
    const float* b2     = (const float*)d_in[9];
    const float* W3     = (const float*)d_in[10];
    const float* a_src3 = (const float*)d_in[11];
    const float* a_dst3 = (const float*)d_in[12];
    const float* b3     = (const float*)d_in[13];
    float* out = (float*)d_out;

    __half* hB16;  cudaGetSymbolAddress((void**)&hB16,  g_hB16);
    __half* w2t16; cudaGetSymbolAddress((void**)&w2t16, g_W2T16);
    float*  als;   cudaGetSymbolAddress((void**)&als,   g_als);
    float*  ald;   cudaGetSymbolAddress((void**)&ald,   g_ald);
    float*  als2;  cudaGetSymbolAddress((void**)&als2,  g_als2);
    float*  ald2;  cudaGetSymbolAddress((void**)&ald2,  g_ald2);

    static bool attr_set = false;
    if (!attr_set) {
        cudaFuncSetAttribute(f16_gemm_kernel,
                             cudaFuncAttributeMaxDynamicSharedMemorySize, 2 * STG16);
        attr_set = true;
    }

    // fold a1 into W1 (needed by prep segment A)
    wtilde_kernel<<<1, 256>>>(W1, a_src1, a_dst1);

    // prep: gemm1+logits | W2 transpose fp16 | M2 fold | edge count
    prep_kernel<<<SEG_A + SEG_B + SEG_C + SEG_D, 256>>>(x, W1, W2,
                                                        a_src2, a_dst2, eidx);
    scan_kernel<<<1, 1024>>>();
    scatter_kernel<<<(E_EDGES + 255) / 256, 256>>>(eidx);

    // layer 1 aggregate (+ layer-2 logits via M2)
    agg_kernel<0><<<N_NODES, 256>>>(als, ald, b1, nullptr, nullptr, nullptr);

    // layer 2: fp16 tensor-core GEMM (fp16 output only)
    dim3 g2(FEAT / 128, (N_NODES + 127) / 128);
    f16_gemm_kernel<<<g2, 256, 2 * STG16>>>(hB16, w2t16, N_NODES);

    // layer 2 aggregate with fused layer-3 projection
    agg_kernel<1><<<N_NODES, 256>>>(als2, ald2, b2, W3, a_src3, a_dst3);

    // layer 3 aggregation (+ scratch re-zero for next replay)
    agg3_kernel<<<(N_NODES * 32 + 255) / 256, 256>>>(b3, out);
}